// round 3
// baseline (speedup 1.0000x reference)
#include <cuda_runtime.h>
#include <cuda_bf16.h>

#define S_   128
#define B_   128
#define C_   256
#define E_   256
#define D_   512
#define EMB_ 256
#define V_   10000
#define T_   32

struct Scratch {
    float pre[2][S_ * B_][E_];          // input-projected sequences (fwd/bwd)
    float enc_out[S_ * B_][2 * E_];
    float enc_part[S_ * B_][D_];
    float h[2][2][B_][E_];              // [dir][parity][b][e]
    float hcat[B_][2 * E_];
    float hdec[B_][D_];
    float hW[B_][D_];
    float scores[B_][S_];
    float x[B_][EMB_ + 2 * E_];         // [emb | weighted]
    float z[B_][D_ + 2 * E_ + EMB_];    // [h_new | weighted | emb]
    float gi[B_][3 * D_];
    float gh[B_][3 * D_];
    unsigned bar_arrive;
    unsigned bar_gen;
};
__device__ Scratch g;

__device__ __forceinline__ float tanh_fast(float x) {
    float e = __expf(2.0f * x);
    return 1.0f - __fdividef(2.0f, e + 1.0f);
}
__device__ __forceinline__ float sig_fast(float x) {
    return __fdividef(1.0f, 1.0f + __expf(-x));
}

// ---------------- grid barrier (co-resident persistent kernel) ---------------
__device__ __forceinline__ void grid_barrier(unsigned nb) {
    __syncthreads();
    if (threadIdx.x == 0) {
        __threadfence();
        unsigned gen = atomicAdd(&g.bar_gen, 0u);
        if (atomicAdd(&g.bar_arrive, 1u) == nb - 1u) {
            g.bar_arrive = 0u;
            __threadfence();
            atomicAdd(&g.bar_gen, 1u);
        } else {
            while (atomicAdd(&g.bar_gen, 0u) == gen) { __nanosleep(64); }
        }
    }
    __syncthreads();
}

// ------------- SGEMM BN=64: C[M,N] = A[M,K] @ B[N,K]^T + bias ----------------
// BM=128, BK=16, 256 threads, 8x4 per-thread tile. M mult of 128, K mult of 16.
__global__ __launch_bounds__(256) void sgemm64(
    const float* __restrict__ A, int lda,
    const float* __restrict__ Bm, int ldb,
    const float* __restrict__ bias,
    float* __restrict__ Cm, long long ldc, int N, int K) {
    __shared__ float As[16][132];
    __shared__ float Bs[16][68];
    int tid = threadIdx.x;
    int tx = tid & 15, ty = tid >> 4;
    int m0 = blockIdx.y * 128;
    int n0 = blockIdx.x * 64;

    float acc[8][4];
#pragma unroll
    for (int i = 0; i < 8; i++)
#pragma unroll
        for (int j = 0; j < 4; j++) acc[i][j] = 0.0f;

    for (int k0 = 0; k0 < K; k0 += 16) {
#pragma unroll
        for (int i = 0; i < 2; i++) {
            int idx = tid + i * 256;
            int m = idx >> 2, kq = idx & 3;
            float4 a = *(const float4*)&A[(size_t)(m0 + m) * lda + k0 + kq * 4];
            As[kq * 4 + 0][m] = a.x; As[kq * 4 + 1][m] = a.y;
            As[kq * 4 + 2][m] = a.z; As[kq * 4 + 3][m] = a.w;
        }
        {
            int n = tid >> 2, kq = tid & 3;
            float4 bv = make_float4(0.f, 0.f, 0.f, 0.f);
            if (n0 + n < N)
                bv = *(const float4*)&Bm[(size_t)(n0 + n) * ldb + k0 + kq * 4];
            Bs[kq * 4 + 0][n] = bv.x; Bs[kq * 4 + 1][n] = bv.y;
            Bs[kq * 4 + 2][n] = bv.z; Bs[kq * 4 + 3][n] = bv.w;
        }
        __syncthreads();
#pragma unroll
        for (int kk = 0; kk < 16; kk++) {
            float4 a0 = *(const float4*)&As[kk][ty * 4];
            float4 a1 = *(const float4*)&As[kk][64 + ty * 4];
            float4 bv = *(const float4*)&Bs[kk][tx * 4];
            float ar[8] = {a0.x, a0.y, a0.z, a0.w, a1.x, a1.y, a1.z, a1.w};
            float br[4] = {bv.x, bv.y, bv.z, bv.w};
#pragma unroll
            for (int i = 0; i < 8; i++)
#pragma unroll
                for (int j = 0; j < 4; j++) acc[i][j] += ar[i] * br[j];
        }
        __syncthreads();
    }
    float bvals[4];
#pragma unroll
    for (int j = 0; j < 4; j++) {
        int n = n0 + tx * 4 + j;
        bvals[j] = (bias != nullptr && n < N) ? bias[n] : 0.0f;
    }
#pragma unroll
    for (int r = 0; r < 8; r++) {
        int m = (r < 4) ? (m0 + ty * 4 + r) : (m0 + 64 + ty * 4 + (r - 4));
#pragma unroll
        for (int j = 0; j < 4; j++) {
            int n = n0 + tx * 4 + j;
            if (n < N) Cm[(size_t)m * ldc + n] = acc[r][j] + bvals[j];
        }
    }
}

// ------------- SGEMM BN=16 (more CTAs for small-N, M=128 GEMMs) --------------
__global__ __launch_bounds__(256) void sgemm16(
    const float* __restrict__ A, int lda,
    const float* __restrict__ Bm, int ldb,
    const float* __restrict__ bias,
    float* __restrict__ Cm, int ldc, int K) {
    __shared__ float As[16][132];
    __shared__ float Bs[16][17];
    int tid = threadIdx.x;
    int tx = tid & 15, ty = tid >> 4;
    int n0 = blockIdx.x * 16;

    float acc[8];
#pragma unroll
    for (int i = 0; i < 8; i++) acc[i] = 0.0f;

    for (int k0 = 0; k0 < K; k0 += 16) {
#pragma unroll
        for (int i = 0; i < 2; i++) {
            int idx = tid + i * 256;
            int m = idx >> 2, kq = idx & 3;
            float4 a = *(const float4*)&A[(size_t)m * lda + k0 + kq * 4];
            As[kq * 4 + 0][m] = a.x; As[kq * 4 + 1][m] = a.y;
            As[kq * 4 + 2][m] = a.z; As[kq * 4 + 3][m] = a.w;
        }
        if (tid < 64) {
            int n = tid >> 2, kq = tid & 3;
            float4 bv = *(const float4*)&Bm[(size_t)(n0 + n) * ldb + k0 + kq * 4];
            Bs[kq * 4 + 0][n] = bv.x; Bs[kq * 4 + 1][n] = bv.y;
            Bs[kq * 4 + 2][n] = bv.z; Bs[kq * 4 + 3][n] = bv.w;
        }
        __syncthreads();
#pragma unroll
        for (int kk = 0; kk < 16; kk++) {
            float4 a0 = *(const float4*)&As[kk][ty * 4];
            float4 a1 = *(const float4*)&As[kk][64 + ty * 4];
            float b = Bs[kk][tx];
            acc[0] += a0.x * b; acc[1] += a0.y * b;
            acc[2] += a0.z * b; acc[3] += a0.w * b;
            acc[4] += a1.x * b; acc[5] += a1.y * b;
            acc[6] += a1.z * b; acc[7] += a1.w * b;
        }
        __syncthreads();
    }
    int n = n0 + tx;
    float bv = (bias != nullptr) ? bias[n] : 0.0f;
#pragma unroll
    for (int r = 0; r < 8; r++) {
        int m = (r < 4) ? (ty * 4 + r) : (64 + ty * 4 + (r - 4));
        Cm[(size_t)m * ldc + n] = acc[r] + bv;
    }
}

// ---------------- encoder recurrence: persistent kernel ----------------------
// 128 CTAs (64 per direction), 256 threads; CTA handles 4 e-cols, all 128 b.
__global__ __launch_bounds__(256, 1) void enc_scan_kernel(
    const float* __restrict__ Whh_f, const float* __restrict__ bhh_f,
    const float* __restrict__ Whh_b, const float* __restrict__ bhh_b) {
    int dir = blockIdx.x >> 6;
    int e0 = (blockIdx.x & 63) * 4;
    const float* Whh = dir ? Whh_b : Whh_f;
    const float* bhh = dir ? bhh_b : bhh_f;

    __shared__ float ws[4][256];
    __shared__ float hs[128][68];
    int tid = threadIdx.x;

    {   // zero both parities of g.h
        float* gh = &g.h[0][0][0][0];
        int base = blockIdx.x * 256 + tid;
#pragma unroll
        for (int i = 0; i < 4; i++) gh[base + i * 32768] = 0.0f;
    }
    {   // 4 Whh rows into smem
        int r = tid >> 6, kv = tid & 63;
        *(float4*)&ws[r][kv * 4] = *(const float4*)&Whh[(e0 + r) * 256 + kv * 4];
    }
    int b = tid & 127;
    int j0 = (tid >> 7) * 2;
    float bh0 = bhh[e0 + j0], bh1 = bhh[e0 + j0 + 1];

    grid_barrier(128);

    for (int t = 0; t < 128; t++) {
        int s = dir ? (127 - t) : t;
        int p = t & 1;
        const float* hin = &g.h[dir][p][0][0];
        float acc0 = 0.f, acc1 = 0.f;
#pragma unroll 1
        for (int c = 0; c < 4; c++) {
#pragma unroll
            for (int i = 0; i < 8; i++) {
                int idx = tid + i * 256;
                int bb = idx >> 4, kv = idx & 15;
                float4 hv = __ldcg((const float4*)&hin[bb * 256 + c * 64 + kv * 4]);
                *(float4*)&hs[bb][kv * 4] = hv;
            }
            __syncthreads();
#pragma unroll
            for (int kv = 0; kv < 16; kv++) {
                float4 hv = *(const float4*)&hs[b][kv * 4];
                float4 w0 = *(const float4*)&ws[j0][c * 64 + kv * 4];
                float4 w1 = *(const float4*)&ws[j0 + 1][c * 64 + kv * 4];
                acc0 += hv.x * w0.x + hv.y * w0.y + hv.z * w0.z + hv.w * w0.w;
                acc1 += hv.x * w1.x + hv.y * w1.y + hv.z * w1.z + hv.w * w1.w;
            }
            __syncthreads();
        }
        float h0 = tanh_fast(g.pre[dir][s * 128 + b][e0 + j0] + acc0 + bh0);
        float h1 = tanh_fast(g.pre[dir][s * 128 + b][e0 + j0 + 1] + acc1 + bh1);
        float* hout = &g.h[dir][1 - p][0][0];
        hout[b * 256 + e0 + j0] = h0;
        hout[b * 256 + e0 + j0 + 1] = h1;
        g.enc_out[s * 128 + b][dir * 256 + e0 + j0] = h0;
        g.enc_out[s * 128 + b][dir * 256 + e0 + j0 + 1] = h1;
        grid_barrier(128);
    }
}

__global__ void concat_h_kernel() {
    int idx = blockIdx.x * 256 + threadIdx.x;   // 65536
    int b = idx >> 9, e = idx & 511;
    g.hcat[b][e] = (e < 256) ? g.h[0][0][b][e] : g.h[1][0][b][e - 256];
}

__global__ void act_hdec_kernel() {             // hdec = tanh(fc_tmp in g.gi)
    int idx = blockIdx.x * 256 + threadIdx.x;   // 65536
    int b = idx >> 9, d = idx & 511;
    g.hdec[b][d] = tanh_fast((&g.gi[0][0])[idx]);
}

// ---------------- decoder step kernels ---------------------------------------
__global__ void embed_kernel(const int* __restrict__ trg,
                             const float* __restrict__ emb, int t) {
    int b = blockIdx.x, e = threadIdx.x;        // 128 x 256
    int tok = trg[b * T_ + t];
    float val = emb[(size_t)tok * EMB_ + e];
    g.x[b][e] = val;
    g.z[b][1024 + e] = val;
}

// scores[b][s] = sum_d tanh(hW[b][d] + enc_part[s][b][d]) * v[d]
__global__ __launch_bounds__(256) void attn_scores_kernel(const float* __restrict__ v) {
    int s = blockIdx.x;
    __shared__ float vs[512];
    int tid = threadIdx.x;
    vs[tid] = v[tid];
    vs[256 + tid] = v[256 + tid];
    __syncthreads();
    int w = tid >> 5, lane = tid & 31;
    for (int bi = 0; bi < 16; bi++) {
        int b = w * 16 + bi;
        const float* ep = &g.enc_part[s * 128 + b][0];
        const float* hw = &g.hW[b][0];
        float val = 0.f;
#pragma unroll
        for (int dd = 0; dd < 16; dd++) {
            int d = lane + dd * 32;
            val += tanh_fast(hw[d] + ep[d]) * vs[d];
        }
#pragma unroll
        for (int o = 16; o > 0; o >>= 1) val += __shfl_xor_sync(0xffffffffu, val, o);
        if (lane == 0) g.scores[b][s] = val;
    }
}

// softmax over S + weighted context -> g.x[:,256:768] and g.z[:,512:1024]
__global__ __launch_bounds__(128) void attn_soft_weighted_kernel() {
    int b = blockIdx.x;
    int tid = threadIdx.x;                      // 128 == S
    __shared__ float sh[128];
    __shared__ float aw[128];
    float xv = g.scores[b][tid];
    sh[tid] = xv;
    __syncthreads();
    for (int o = 64; o > 0; o >>= 1) {
        if (tid < o) sh[tid] = fmaxf(sh[tid], sh[tid + o]);
        __syncthreads();
    }
    float mx = sh[0];
    __syncthreads();
    float e = __expf(xv - mx);
    sh[tid] = e;
    __syncthreads();
    for (int o = 64; o > 0; o >>= 1) {
        if (tid < o) sh[tid] += sh[tid + o];
        __syncthreads();
    }
    float inv = 1.0f / sh[0];
    aw[tid] = e * inv;
    __syncthreads();
    float acc[4] = {0.f, 0.f, 0.f, 0.f};
    for (int s2 = 0; s2 < 128; s2++) {
        float as = aw[s2];
        const float* eo = &g.enc_out[s2 * 128 + b][0];
#pragma unroll
        for (int i = 0; i < 4; i++) acc[i] += as * eo[tid + i * 128];
    }
#pragma unroll
    for (int i = 0; i < 4; i++) {
        int ee = tid + i * 128;
        g.x[b][256 + ee] = acc[i];
        g.z[b][512 + ee] = acc[i];
    }
}

__global__ void gru_combine_kernel() {
    int idx = blockIdx.x * 256 + threadIdx.x;   // 65536
    int b = idx >> 9, d = idx & 511;
    float r = sig_fast(g.gi[b][d] + g.gh[b][d]);
    float zz = sig_fast(g.gi[b][512 + d] + g.gh[b][512 + d]);
    float n = tanh_fast(g.gi[b][1024 + d] + r * g.gh[b][1024 + d]);
    float h = g.hdec[b][d];
    float hn = (1.0f - zz) * n + zz * h;
    g.hdec[b][d] = hn;
    g.z[b][d] = hn;
}

__global__ __launch_bounds__(256) void out_softmax_kernel(float* __restrict__ outp, int t) {
    int b = blockIdx.x;
    int tid = threadIdx.x;
    float* row = outp + ((size_t)(b * T_ + t)) * V_;
    __shared__ float sh[256];
    float mx = -1e30f;
    for (int i = tid; i < V_; i += 256) mx = fmaxf(mx, row[i]);
    sh[tid] = mx;
    __syncthreads();
    for (int o = 128; o > 0; o >>= 1) {
        if (tid < o) sh[tid] = fmaxf(sh[tid], sh[tid + o]);
        __syncthreads();
    }
    mx = sh[0];
    __syncthreads();
    float sum = 0.f;
    for (int i = tid; i < V_; i += 256) {
        float e = __expf(row[i] - mx);
        row[i] = e;
        sum += e;
    }
    sh[tid] = sum;
    __syncthreads();
    for (int o = 128; o > 0; o >>= 1) {
        if (tid < o) sh[tid] += sh[tid + o];
        __syncthreads();
    }
    float inv = 1.0f / sh[0];
    for (int i = tid; i < V_; i += 256) row[i] *= inv;
}

// -----------------------------------------------------------------------------
extern "C" void kernel_launch(void* const* d_in, const int* in_sizes, int n_in,
                              void* d_out, int out_size) {
    Scratch* gp;
    cudaGetSymbolAddress((void**)&gp, g);

    const float* src      = (const float*)d_in[0];
    const int*   trg      = (const int*)  d_in[1];
    const float* Wih_f    = (const float*)d_in[2];
    const float* Whh_f    = (const float*)d_in[3];
    const float* bih_f    = (const float*)d_in[4];
    const float* bhh_f    = (const float*)d_in[5];
    const float* Wih_b    = (const float*)d_in[6];
    const float* Whh_b    = (const float*)d_in[7];
    const float* bih_b    = (const float*)d_in[8];
    const float* bhh_b    = (const float*)d_in[9];
    const float* fcW      = (const float*)d_in[10];
    const float* fcb      = (const float*)d_in[11];
    const float* attn_W   = (const float*)d_in[12];
    const float* attn_b   = (const float*)d_in[13];
    const float* attn_v   = (const float*)d_in[14];
    const float* emb      = (const float*)d_in[15];
    const float* gru_Wih  = (const float*)d_in[16];
    const float* gru_Whh  = (const float*)d_in[17];
    const float* gru_bih  = (const float*)d_in[18];
    const float* gru_bhh  = (const float*)d_in[19];
    const float* out_W    = (const float*)d_in[20];
    const float* out_b    = (const float*)d_in[21];
    float* out = (float*)d_out;

    float* pre_f    = &gp->pre[0][0][0];
    float* pre_b    = &gp->pre[1][0][0];
    float* enc_out  = &gp->enc_out[0][0];
    float* enc_part = &gp->enc_part[0][0];
    float* hcat     = &gp->hcat[0][0];
    float* hdec     = &gp->hdec[0][0];
    float* hW       = &gp->hW[0][0];
    float* xbuf     = &gp->x[0][0];
    float* zbuf     = &gp->z[0][0];
    float* gi       = &gp->gi[0][0];
    float* gh       = &gp->gh[0][0];

    // ---- encoder ----
    sgemm64<<<dim3(4, 128), 256>>>(src, C_, Wih_f, C_, bih_f, pre_f, E_, E_, C_);
    sgemm64<<<dim3(4, 128), 256>>>(src, C_, Wih_b, C_, bih_b, pre_b, E_, E_, C_);
    enc_scan_kernel<<<128, 256>>>(Whh_f, bhh_f, Whh_b, bhh_b);
    concat_h_kernel<<<256, 256>>>();
    sgemm16<<<32, 256>>>(hcat, 512, fcW, 512, fcb, gi, 512, 512);   // fc tmp in gi
    act_hdec_kernel<<<256, 256>>>();
    sgemm64<<<dim3(8, 128), 256>>>(enc_out, 512, attn_W + 512, 1024, attn_b,
                                   enc_part, D_, D_, 512);

    // ---- decoder ----
    for (int t = 0; t < T_; t++) {
        embed_kernel<<<128, 256>>>(trg, emb, t);
        sgemm16<<<32, 256>>>(hdec, 512, attn_W, 1024, nullptr, hW, 512, 512);
        attn_scores_kernel<<<128, 256>>>(attn_v);
        attn_soft_weighted_kernel<<<128, 128>>>();
        sgemm16<<<96, 256>>>(xbuf, 768, gru_Wih, 768, gru_bih, gi, 1536, 768);
        sgemm16<<<96, 256>>>(hdec, 512, gru_Whh, 512, gru_bhh, gh, 1536, 512);
        gru_combine_kernel<<<256, 256>>>();
        sgemm64<<<dim3(157, 1), 256>>>(zbuf, 1280, out_W, 1280, out_b,
                                       out + (size_t)t * V_, (long long)T_ * V_,
                                       V_, 1280);
        out_softmax_kernel<<<128, 256>>>(out, t);
    }
}

// round 4
// speedup vs baseline: 1.3315x; 1.3315x over previous
#include <cuda_runtime.h>
#include <cuda_bf16.h>
#include <cstdint>

#define S_   128
#define B_   128
#define C_   256
#define E_   256
#define D_   512
#define EMB_ 256
#define V_   10000
#define T_   32

struct Scratch {
    float pre[2][S_ * B_][E_];          // input-projected sequences (fwd/bwd)
    float enc_out[S_ * B_][2 * E_];
    float enc_part[S_ * B_][D_];
    float h[2][2][B_][E_];              // [dir][parity][b][e]
    float hcat[B_][2 * E_];
    float hdec[B_][D_];
    float hW[B_][D_];
    float scores[B_][S_];
    float x[B_][EMB_ + 2 * E_];         // [emb | weighted]
    float z[B_][D_ + 2 * E_ + EMB_];    // [h_new | weighted | emb]
    float gi[B_][3 * D_];
    float gh[B_][3 * D_];
    unsigned bar_arrive;
    unsigned bar_gen;
};
__device__ Scratch g;

__device__ __forceinline__ float tanh_fast(float x) {
    float e = __expf(2.0f * x);
    return 1.0f - __fdividef(2.0f, e + 1.0f);
}
__device__ __forceinline__ float sig_fast(float x) {
    return __fdividef(1.0f, 1.0f + __expf(-x));
}
__device__ __forceinline__ float to_tf32(float x) {
    uint32_t u;
    asm("cvt.rna.tf32.f32 %0, %1;" : "=r"(u) : "f"(x));
    return __uint_as_float(u);
}
__device__ __forceinline__ void mma_tf32(float c[4], const uint32_t a[4],
                                         const uint32_t b[2]) {
    asm volatile(
        "mma.sync.aligned.m16n8k8.row.col.f32.tf32.tf32.f32 "
        "{%0,%1,%2,%3}, {%4,%5,%6,%7}, {%8,%9}, {%0,%1,%2,%3};\n"
        : "+f"(c[0]), "+f"(c[1]), "+f"(c[2]), "+f"(c[3])
        : "r"(a[0]), "r"(a[1]), "r"(a[2]), "r"(a[3]), "r"(b[0]), "r"(b[1]));
}

// ---------------- grid barrier (co-resident persistent kernel) ---------------
__device__ __forceinline__ void grid_barrier(unsigned nb) {
    __syncthreads();
    if (threadIdx.x == 0) {
        __threadfence();
        unsigned gen = atomicAdd(&g.bar_gen, 0u);
        if (atomicAdd(&g.bar_arrive, 1u) == nb - 1u) {
            g.bar_arrive = 0u;
            __threadfence();
            atomicAdd(&g.bar_gen, 1u);
        } else {
            while (atomicAdd(&g.bar_gen, 0u) == gen) { __nanosleep(64); }
        }
    }
    __syncthreads();
}

// ------------- TF32 tensor GEMM: C[M,N] = A[M,K] @ B[N,K]^T + bias -----------
// BM=128, BN=64, BK=32, 256 threads (8 warps as 2M x 4N, warp tile 64x16).
// M % 128 == 0, K % 32 == 0. N guarded.
__global__ __launch_bounds__(256) void tgemm_tf32(
    const float* __restrict__ A, int lda,
    const float* __restrict__ Bm, int ldb,
    const float* __restrict__ bias,
    float* __restrict__ Cm, long long ldc, int N, int K) {
    __shared__ float As[128][36];
    __shared__ float Bs[64][36];
    const int tid = threadIdx.x, lane = tid & 31, wid = tid >> 5;
    const int m0 = blockIdx.y * 128, n0 = blockIdx.x * 64;
    const int wm = (wid & 1) * 64, wn = (wid >> 1) * 16;

    const int am = tid >> 1, akh = (tid & 1) * 16;   // A stage: 16 floats/thread
    const int bn = tid >> 2, bkq = (tid & 3) * 8;    // B stage: 8 floats/thread
    const bool bok = (n0 + bn) < N;

    float4 pa[4], pb[2];
    {
        const float* Ap = A + (size_t)(m0 + am) * lda + akh;
#pragma unroll
        for (int q = 0; q < 4; q++) pa[q] = *(const float4*)(Ap + q * 4);
        const float* Bp = Bm + (size_t)(n0 + bn) * ldb + bkq;
#pragma unroll
        for (int q = 0; q < 2; q++)
            pb[q] = bok ? *(const float4*)(Bp + q * 4)
                        : make_float4(0.f, 0.f, 0.f, 0.f);
    }

    float acc[4][2][4];
#pragma unroll
    for (int mt = 0; mt < 4; mt++)
#pragma unroll
        for (int nt = 0; nt < 2; nt++)
#pragma unroll
            for (int q = 0; q < 4; q++) acc[mt][nt][q] = 0.0f;

    const int KT = K / 32;
    for (int kt = 0; kt < KT; kt++) {
#pragma unroll
        for (int q = 0; q < 4; q++) {
            As[am][akh + q * 4 + 0] = to_tf32(pa[q].x);
            As[am][akh + q * 4 + 1] = to_tf32(pa[q].y);
            As[am][akh + q * 4 + 2] = to_tf32(pa[q].z);
            As[am][akh + q * 4 + 3] = to_tf32(pa[q].w);
        }
#pragma unroll
        for (int q = 0; q < 2; q++) {
            Bs[bn][bkq + q * 4 + 0] = to_tf32(pb[q].x);
            Bs[bn][bkq + q * 4 + 1] = to_tf32(pb[q].y);
            Bs[bn][bkq + q * 4 + 2] = to_tf32(pb[q].z);
            Bs[bn][bkq + q * 4 + 3] = to_tf32(pb[q].w);
        }
        __syncthreads();

        if (kt + 1 < KT) {
            int k0 = (kt + 1) * 32;
            const float* Ap = A + (size_t)(m0 + am) * lda + k0 + akh;
#pragma unroll
            for (int q = 0; q < 4; q++) pa[q] = *(const float4*)(Ap + q * 4);
            const float* Bp = Bm + (size_t)(n0 + bn) * ldb + k0 + bkq;
#pragma unroll
            for (int q = 0; q < 2; q++)
                pb[q] = bok ? *(const float4*)(Bp + q * 4)
                            : make_float4(0.f, 0.f, 0.f, 0.f);
        }

        const int r = lane >> 2, c = lane & 3;
#pragma unroll
        for (int kc = 0; kc < 32; kc += 8) {
            uint32_t af[4][4], bf[2][2];
#pragma unroll
            for (int mt = 0; mt < 4; mt++) {
                int rb = wm + mt * 16;
                af[mt][0] = __float_as_uint(As[rb + r][kc + c]);
                af[mt][1] = __float_as_uint(As[rb + r + 8][kc + c]);
                af[mt][2] = __float_as_uint(As[rb + r][kc + c + 4]);
                af[mt][3] = __float_as_uint(As[rb + r + 8][kc + c + 4]);
            }
#pragma unroll
            for (int nt = 0; nt < 2; nt++) {
                int cb = wn + nt * 8;
                bf[nt][0] = __float_as_uint(Bs[cb + r][kc + c]);
                bf[nt][1] = __float_as_uint(Bs[cb + r][kc + c + 4]);
            }
#pragma unroll
            for (int mt = 0; mt < 4; mt++)
#pragma unroll
                for (int nt = 0; nt < 2; nt++)
                    mma_tf32(acc[mt][nt], af[mt], bf[nt]);
        }
        __syncthreads();
    }

    const int r = lane >> 2, c2 = (lane & 3) * 2;
#pragma unroll
    for (int mt = 0; mt < 4; mt++) {
#pragma unroll
        for (int nt = 0; nt < 2; nt++) {
            int col = n0 + wn + nt * 8 + c2;
            if (col < N) {
                float b0 = (bias != nullptr) ? bias[col] : 0.0f;
                float b1 = (bias != nullptr) ? bias[col + 1] : 0.0f;
                int row0 = m0 + wm + mt * 16 + r;
                float2 v0 = make_float2(acc[mt][nt][0] + b0, acc[mt][nt][1] + b1);
                float2 v1 = make_float2(acc[mt][nt][2] + b0, acc[mt][nt][3] + b1);
                *(float2*)&Cm[(size_t)row0 * ldc + col] = v0;
                *(float2*)&Cm[(size_t)(row0 + 8) * ldc + col] = v1;
            }
        }
    }
}

// ------------- SGEMM BN=16 (fp32, for recurrence-critical small GEMMs) -------
__global__ __launch_bounds__(256) void sgemm16(
    const float* __restrict__ A, int lda,
    const float* __restrict__ Bm, int ldb,
    const float* __restrict__ bias,
    float* __restrict__ Cm, int ldc, int K) {
    __shared__ float As[16][132];
    __shared__ float Bs[16][17];
    int tid = threadIdx.x;
    int tx = tid & 15, ty = tid >> 4;
    int n0 = blockIdx.x * 16;

    float acc[8];
#pragma unroll
    for (int i = 0; i < 8; i++) acc[i] = 0.0f;

    for (int k0 = 0; k0 < K; k0 += 16) {
#pragma unroll
        for (int i = 0; i < 2; i++) {
            int idx = tid + i * 256;
            int m = idx >> 2, kq = idx & 3;
            float4 a = *(const float4*)&A[(size_t)m * lda + k0 + kq * 4];
            As[kq * 4 + 0][m] = a.x; As[kq * 4 + 1][m] = a.y;
            As[kq * 4 + 2][m] = a.z; As[kq * 4 + 3][m] = a.w;
        }
        if (tid < 64) {
            int n = tid >> 2, kq = tid & 3;
            float4 bv = *(const float4*)&Bm[(size_t)(n0 + n) * ldb + k0 + kq * 4];
            Bs[kq * 4 + 0][n] = bv.x; Bs[kq * 4 + 1][n] = bv.y;
            Bs[kq * 4 + 2][n] = bv.z; Bs[kq * 4 + 3][n] = bv.w;
        }
        __syncthreads();
#pragma unroll
        for (int kk = 0; kk < 16; kk++) {
            float4 a0 = *(const float4*)&As[kk][ty * 4];
            float4 a1 = *(const float4*)&As[kk][64 + ty * 4];
            float b = Bs[kk][tx];
            acc[0] += a0.x * b; acc[1] += a0.y * b;
            acc[2] += a0.z * b; acc[3] += a0.w * b;
            acc[4] += a1.x * b; acc[5] += a1.y * b;
            acc[6] += a1.z * b; acc[7] += a1.w * b;
        }
        __syncthreads();
    }
    int n = n0 + tx;
    float bv = (bias != nullptr) ? bias[n] : 0.0f;
#pragma unroll
    for (int r = 0; r < 8; r++) {
        int m = (r < 4) ? (ty * 4 + r) : (64 + ty * 4 + (r - 4));
        Cm[(size_t)m * ldc + n] = acc[r] + bv;
    }
}

// ---------------- encoder recurrence: persistent kernel ----------------------
__global__ __launch_bounds__(256, 1) void enc_scan_kernel(
    const float* __restrict__ Whh_f, const float* __restrict__ bhh_f,
    const float* __restrict__ Whh_b, const float* __restrict__ bhh_b) {
    int dir = blockIdx.x >> 6;
    int e0 = (blockIdx.x & 63) * 4;
    const float* Whh = dir ? Whh_b : Whh_f;
    const float* bhh = dir ? bhh_b : bhh_f;

    __shared__ float ws[4][256];
    __shared__ float hs[128][68];
    int tid = threadIdx.x;

    {
        float* gh = &g.h[0][0][0][0];
        int base = blockIdx.x * 256 + tid;
#pragma unroll
        for (int i = 0; i < 4; i++) gh[base + i * 32768] = 0.0f;
    }
    {
        int r = tid >> 6, kv = tid & 63;
        *(float4*)&ws[r][kv * 4] = *(const float4*)&Whh[(e0 + r) * 256 + kv * 4];
    }
    int b = tid & 127;
    int j0 = (tid >> 7) * 2;
    float bh0 = bhh[e0 + j0], bh1 = bhh[e0 + j0 + 1];

    grid_barrier(128);

    for (int t = 0; t < 128; t++) {
        int s = dir ? (127 - t) : t;
        int p = t & 1;
        const float* hin = &g.h[dir][p][0][0];
        float acc0 = 0.f, acc1 = 0.f;
#pragma unroll 1
        for (int c = 0; c < 4; c++) {
#pragma unroll
            for (int i = 0; i < 8; i++) {
                int idx = tid + i * 256;
                int bb = idx >> 4, kv = idx & 15;
                float4 hv = __ldcg((const float4*)&hin[bb * 256 + c * 64 + kv * 4]);
                *(float4*)&hs[bb][kv * 4] = hv;
            }
            __syncthreads();
#pragma unroll
            for (int kv = 0; kv < 16; kv++) {
                float4 hv = *(const float4*)&hs[b][kv * 4];
                float4 w0 = *(const float4*)&ws[j0][c * 64 + kv * 4];
                float4 w1 = *(const float4*)&ws[j0 + 1][c * 64 + kv * 4];
                acc0 += hv.x * w0.x + hv.y * w0.y + hv.z * w0.z + hv.w * w0.w;
                acc1 += hv.x * w1.x + hv.y * w1.y + hv.z * w1.z + hv.w * w1.w;
            }
            __syncthreads();
        }
        float h0 = tanh_fast(g.pre[dir][s * 128 + b][e0 + j0] + acc0 + bh0);
        float h1 = tanh_fast(g.pre[dir][s * 128 + b][e0 + j0 + 1] + acc1 + bh1);
        float* hout = &g.h[dir][1 - p][0][0];
        hout[b * 256 + e0 + j0] = h0;
        hout[b * 256 + e0 + j0 + 1] = h1;
        g.enc_out[s * 128 + b][dir * 256 + e0 + j0] = h0;
        g.enc_out[s * 128 + b][dir * 256 + e0 + j0 + 1] = h1;
        grid_barrier(128);
    }
}

__global__ void concat_h_kernel() {
    int idx = blockIdx.x * 256 + threadIdx.x;   // 65536
    int b = idx >> 9, e = idx & 511;
    g.hcat[b][e] = (e < 256) ? g.h[0][0][b][e] : g.h[1][0][b][e - 256];
}

__global__ void act_hdec_kernel() {             // hdec = tanh(fc_tmp in g.gi)
    int idx = blockIdx.x * 256 + threadIdx.x;   // 65536
    int b = idx >> 9, d = idx & 511;
    g.hdec[b][d] = tanh_fast((&g.gi[0][0])[idx]);
}

// ---------------- decoder step kernels ---------------------------------------
__global__ void embed_kernel(const int* __restrict__ trg,
                             const float* __restrict__ emb, int t) {
    int b = blockIdx.x, e = threadIdx.x;        // 128 x 256
    int tok = trg[b * T_ + t];
    float val = emb[(size_t)tok * EMB_ + e];
    g.x[b][e] = val;
    g.z[b][1024 + e] = val;
}

__global__ __launch_bounds__(256) void attn_scores_kernel(const float* __restrict__ v) {
    int s = blockIdx.x;
    __shared__ float vs[512];
    int tid = threadIdx.x;
    vs[tid] = v[tid];
    vs[256 + tid] = v[256 + tid];
    __syncthreads();
    int w = tid >> 5, lane = tid & 31;
    for (int bi = 0; bi < 16; bi++) {
        int b = w * 16 + bi;
        const float* ep = &g.enc_part[s * 128 + b][0];
        const float* hw = &g.hW[b][0];
        float val = 0.f;
#pragma unroll
        for (int dd = 0; dd < 16; dd++) {
            int d = lane + dd * 32;
            val += tanh_fast(hw[d] + ep[d]) * vs[d];
        }
#pragma unroll
        for (int o = 16; o > 0; o >>= 1) val += __shfl_xor_sync(0xffffffffu, val, o);
        if (lane == 0) g.scores[b][s] = val;
    }
}

__global__ __launch_bounds__(128) void attn_soft_weighted_kernel() {
    int b = blockIdx.x;
    int tid = threadIdx.x;                      // 128 == S
    __shared__ float sh[128];
    __shared__ float aw[128];
    float xv = g.scores[b][tid];
    sh[tid] = xv;
    __syncthreads();
    for (int o = 64; o > 0; o >>= 1) {
        if (tid < o) sh[tid] = fmaxf(sh[tid], sh[tid + o]);
        __syncthreads();
    }
    float mx = sh[0];
    __syncthreads();
    float e = __expf(xv - mx);
    sh[tid] = e;
    __syncthreads();
    for (int o = 64; o > 0; o >>= 1) {
        if (tid < o) sh[tid] += sh[tid + o];
        __syncthreads();
    }
    float inv = 1.0f / sh[0];
    aw[tid] = e * inv;
    __syncthreads();
    float acc[4] = {0.f, 0.f, 0.f, 0.f};
    for (int s2 = 0; s2 < 128; s2++) {
        float as = aw[s2];
        const float* eo = &g.enc_out[s2 * 128 + b][0];
#pragma unroll
        for (int i = 0; i < 4; i++) acc[i] += as * eo[tid + i * 128];
    }
#pragma unroll
    for (int i = 0; i < 4; i++) {
        int ee = tid + i * 128;
        g.x[b][256 + ee] = acc[i];
        g.z[b][512 + ee] = acc[i];
    }
}

__global__ void gru_combine_kernel() {
    int idx = blockIdx.x * 256 + threadIdx.x;   // 65536
    int b = idx >> 9, d = idx & 511;
    float r = sig_fast(g.gi[b][d] + g.gh[b][d]);
    float zz = sig_fast(g.gi[b][512 + d] + g.gh[b][512 + d]);
    float n = tanh_fast(g.gi[b][1024 + d] + r * g.gh[b][1024 + d]);
    float h = g.hdec[b][d];
    float hn = (1.0f - zz) * n + zz * h;
    g.hdec[b][d] = hn;
    g.z[b][d] = hn;
}

// single-pass register-resident softmax over V=10000
__global__ __launch_bounds__(256) void out_softmax_kernel(float* __restrict__ outp, int t) {
    int b = blockIdx.x;
    int tid = threadIdx.x;
    float* row = outp + ((size_t)(b * T_ + t)) * V_;
    __shared__ float sh[256];
    float r[40];
    float mx = -1e30f;
#pragma unroll
    for (int j = 0; j < 40; j++) {
        int i = tid + j * 256;
        r[j] = (i < V_) ? row[i] : -1e30f;
        mx = fmaxf(mx, r[j]);
    }
    sh[tid] = mx;
    __syncthreads();
    for (int o = 128; o > 0; o >>= 1) {
        if (tid < o) sh[tid] = fmaxf(sh[tid], sh[tid + o]);
        __syncthreads();
    }
    mx = sh[0];
    __syncthreads();
    float sum = 0.f;
#pragma unroll
    for (int j = 0; j < 40; j++) {
        r[j] = __expf(r[j] - mx);
        sum += r[j];
    }
    sh[tid] = sum;
    __syncthreads();
    for (int o = 128; o > 0; o >>= 1) {
        if (tid < o) sh[tid] += sh[tid + o];
        __syncthreads();
    }
    float inv = 1.0f / sh[0];
#pragma unroll
    for (int j = 0; j < 40; j++) {
        int i = tid + j * 256;
        if (i < V_) row[i] = r[j] * inv;
    }
}

// -----------------------------------------------------------------------------
extern "C" void kernel_launch(void* const* d_in, const int* in_sizes, int n_in,
                              void* d_out, int out_size) {
    Scratch* gp;
    cudaGetSymbolAddress((void**)&gp, g);

    const float* src      = (const float*)d_in[0];
    const int*   trg      = (const int*)  d_in[1];
    const float* Wih_f    = (const float*)d_in[2];
    const float* Whh_f    = (const float*)d_in[3];
    const float* bih_f    = (const float*)d_in[4];
    const float* bhh_f    = (const float*)d_in[5];
    const float* Wih_b    = (const float*)d_in[6];
    const float* Whh_b    = (const float*)d_in[7];
    const float* bih_b    = (const float*)d_in[8];
    const float* bhh_b    = (const float*)d_in[9];
    const float* fcW      = (const float*)d_in[10];
    const float* fcb      = (const float*)d_in[11];
    const float* attn_W   = (const float*)d_in[12];
    const float* attn_b   = (const float*)d_in[13];
    const float* attn_v   = (const float*)d_in[14];
    const float* emb      = (const float*)d_in[15];
    const float* gru_Wih  = (const float*)d_in[16];
    const float* gru_Whh  = (const float*)d_in[17];
    const float* gru_bih  = (const float*)d_in[18];
    const float* gru_bhh  = (const float*)d_in[19];
    const float* out_W    = (const float*)d_in[20];
    const float* out_b    = (const float*)d_in[21];
    float* out = (float*)d_out;

    float* pre_f    = &gp->pre[0][0][0];
    float* pre_b    = &gp->pre[1][0][0];
    float* enc_out  = &gp->enc_out[0][0];
    float* enc_part = &gp->enc_part[0][0];
    float* hcat     = &gp->hcat[0][0];
    float* hdec     = &gp->hdec[0][0];
    float* hW       = &gp->hW[0][0];
    float* xbuf     = &gp->x[0][0];
    float* zbuf     = &gp->z[0][0];
    float* gi       = &gp->gi[0][0];
    float* gh       = &gp->gh[0][0];

    // ---- encoder ----
    tgemm_tf32<<<dim3(4, 128), 256>>>(src, C_, Wih_f, C_, bih_f, pre_f, E_, E_, C_);
    tgemm_tf32<<<dim3(4, 128), 256>>>(src, C_, Wih_b, C_, bih_b, pre_b, E_, E_, C_);
    enc_scan_kernel<<<128, 256>>>(Whh_f, bhh_f, Whh_b, bhh_b);
    concat_h_kernel<<<256, 256>>>();
    sgemm16<<<32, 256>>>(hcat, 512, fcW, 512, fcb, gi, 512, 512);   // fc tmp in gi
    act_hdec_kernel<<<256, 256>>>();
    tgemm_tf32<<<dim3(8, 128), 256>>>(enc_out, 512, attn_W + 512, 1024, attn_b,
                                      enc_part, D_, D_, 512);

    // ---- decoder ----
    for (int t = 0; t < T_; t++) {
        embed_kernel<<<128, 256>>>(trg, emb, t);
        sgemm16<<<32, 256>>>(hdec, 512, attn_W, 1024, nullptr, hW, 512, 512);
        attn_scores_kernel<<<128, 256>>>(attn_v);
        attn_soft_weighted_kernel<<<128, 128>>>();
        sgemm16<<<96, 256>>>(xbuf, 768, gru_Wih, 768, gru_bih, gi, 1536, 768);
        sgemm16<<<96, 256>>>(hdec, 512, gru_Whh, 512, gru_bhh, gh, 1536, 512);
        gru_combine_kernel<<<256, 256>>>();
        tgemm_tf32<<<dim3(157, 1), 256>>>(zbuf, 1280, out_W, 1280, out_b,
                                          out + (size_t)t * V_, (long long)T_ * V_,
                                          V_, 1280);
        out_softmax_kernel<<<128, 256>>>(out, t);
    }
}

// round 7
// speedup vs baseline: 1.6787x; 1.2608x over previous
#include <cuda_runtime.h>
#include <cuda_bf16.h>
#include <cstdint>

#define S_   128
#define B_   128
#define C_   256
#define E_   256
#define D_   512
#define EMB_ 256
#define V_   10000
#define T_   32

struct Scratch {
    float pre[2][S_ * B_][E_];          // input-projected sequences (fwd/bwd)
    float enc_out[S_ * B_][2 * E_];
    float enc_part[S_ * B_][D_];
    float h[2][2][B_][E_];              // [dir][parity][b][e]
    float hcat[B_][2 * E_];
    float hdec[B_][D_];
    float hW[B_][D_];
    float x[B_][EMB_ + 2 * E_];         // [emb | weighted]
    float z[B_][D_ + 2 * E_ + EMB_];    // [h_new | weighted | emb]
    float gi[B_][3 * D_];
    float gh[B_][3 * D_];
    unsigned bar_arrive;
    unsigned bar_gen;
};
__device__ Scratch g;

__device__ __forceinline__ float tanh_fast(float x) {
    float e = __expf(2.0f * x);
    return 1.0f - __fdividef(2.0f, e + 1.0f);
}
__device__ __forceinline__ float sig_fast(float x) {
    return __fdividef(1.0f, 1.0f + __expf(-x));
}
__device__ __forceinline__ float to_tf32(float x) {
    uint32_t u;
    asm("cvt.rna.tf32.f32 %0, %1;" : "=r"(u) : "f"(x));
    return __uint_as_float(u);
}
__device__ __forceinline__ void mma_tf32(float c[4], const uint32_t a[4],
                                         const uint32_t b[2]) {
    asm volatile(
        "mma.sync.aligned.m16n8k8.row.col.f32.tf32.tf32.f32 "
        "{%0,%1,%2,%3}, {%4,%5,%6,%7}, {%8,%9}, {%0,%1,%2,%3};\n"
        : "+f"(c[0]), "+f"(c[1]), "+f"(c[2]), "+f"(c[3])
        : "r"(a[0]), "r"(a[1]), "r"(a[2]), "r"(a[3]), "r"(b[0]), "r"(b[1]));
}

// ---------------- grid barrier (co-resident persistent kernel) ---------------
__device__ __forceinline__ void grid_barrier(unsigned nb) {
    __syncthreads();
    if (threadIdx.x == 0) {
        __threadfence();
        unsigned gen = atomicAdd(&g.bar_gen, 0u);
        if (atomicAdd(&g.bar_arrive, 1u) == nb - 1u) {
            g.bar_arrive = 0u;
            __threadfence();
            atomicAdd(&g.bar_gen, 1u);
        } else {
            while (atomicAdd(&g.bar_gen, 0u) == gen) { __nanosleep(64); }
        }
    }
    __syncthreads();
}

// ------------- TF32 tensor GEMM: C[M,N] = A[M,K] @ B[N,K]^T + bias -----------
// BM=128, BN=64, BK=32, 256 threads (8 warps as 2M x 4N, warp tile 64x16).
__global__ __launch_bounds__(256) void tgemm_tf32(
    const float* __restrict__ A, int lda,
    const float* __restrict__ Bm, int ldb,
    const float* __restrict__ bias,
    float* __restrict__ Cm, long long ldc, int N, int K) {
    __shared__ float As[128][36];
    __shared__ float Bs[64][36];
    const int tid = threadIdx.x, lane = tid & 31, wid = tid >> 5;
    const int m0 = blockIdx.y * 128, n0 = blockIdx.x * 64;
    const int wm = (wid & 1) * 64, wn = (wid >> 1) * 16;

    const int am = tid >> 1, akh = (tid & 1) * 16;
    const int bn = tid >> 2, bkq = (tid & 3) * 8;
    const bool bok = (n0 + bn) < N;

    float4 pa[4], pb[2];
    {
        const float* Ap = A + (size_t)(m0 + am) * lda + akh;
#pragma unroll
        for (int q = 0; q < 4; q++) pa[q] = *(const float4*)(Ap + q * 4);
        const float* Bp = Bm + (size_t)(n0 + bn) * ldb + bkq;
#pragma unroll
        for (int q = 0; q < 2; q++)
            pb[q] = bok ? *(const float4*)(Bp + q * 4)
                        : make_float4(0.f, 0.f, 0.f, 0.f);
    }

    float acc[4][2][4];
#pragma unroll
    for (int mt = 0; mt < 4; mt++)
#pragma unroll
        for (int nt = 0; nt < 2; nt++)
#pragma unroll
            for (int q = 0; q < 4; q++) acc[mt][nt][q] = 0.0f;

    const int KT = K / 32;
    for (int kt = 0; kt < KT; kt++) {
#pragma unroll
        for (int q = 0; q < 4; q++) {
            As[am][akh + q * 4 + 0] = to_tf32(pa[q].x);
            As[am][akh + q * 4 + 1] = to_tf32(pa[q].y);
            As[am][akh + q * 4 + 2] = to_tf32(pa[q].z);
            As[am][akh + q * 4 + 3] = to_tf32(pa[q].w);
        }
#pragma unroll
        for (int q = 0; q < 2; q++) {
            Bs[bn][bkq + q * 4 + 0] = to_tf32(pb[q].x);
            Bs[bn][bkq + q * 4 + 1] = to_tf32(pb[q].y);
            Bs[bn][bkq + q * 4 + 2] = to_tf32(pb[q].z);
            Bs[bn][bkq + q * 4 + 3] = to_tf32(pb[q].w);
        }
        __syncthreads();

        if (kt + 1 < KT) {
            int k0 = (kt + 1) * 32;
            const float* Ap = A + (size_t)(m0 + am) * lda + k0 + akh;
#pragma unroll
            for (int q = 0; q < 4; q++) pa[q] = *(const float4*)(Ap + q * 4);
            const float* Bp = Bm + (size_t)(n0 + bn) * ldb + k0 + bkq;
#pragma unroll
            for (int q = 0; q < 2; q++)
                pb[q] = bok ? *(const float4*)(Bp + q * 4)
                            : make_float4(0.f, 0.f, 0.f, 0.f);
        }

        const int r = lane >> 2, c = lane & 3;
#pragma unroll
        for (int kc = 0; kc < 32; kc += 8) {
            uint32_t af[4][4], bf[2][2];
#pragma unroll
            for (int mt = 0; mt < 4; mt++) {
                int rb = wm + mt * 16;
                af[mt][0] = __float_as_uint(As[rb + r][kc + c]);
                af[mt][1] = __float_as_uint(As[rb + r + 8][kc + c]);
                af[mt][2] = __float_as_uint(As[rb + r][kc + c + 4]);
                af[mt][3] = __float_as_uint(As[rb + r + 8][kc + c + 4]);
            }
#pragma unroll
            for (int nt = 0; nt < 2; nt++) {
                int cb = wn + nt * 8;
                bf[nt][0] = __float_as_uint(Bs[cb + r][kc + c]);
                bf[nt][1] = __float_as_uint(Bs[cb + r][kc + c + 4]);
            }
#pragma unroll
            for (int mt = 0; mt < 4; mt++)
#pragma unroll
                for (int nt = 0; nt < 2; nt++)
                    mma_tf32(acc[mt][nt], af[mt], bf[nt]);
        }
        __syncthreads();
    }

    const int r = lane >> 2, c2 = (lane & 3) * 2;
#pragma unroll
    for (int mt = 0; mt < 4; mt++) {
#pragma unroll
        for (int nt = 0; nt < 2; nt++) {
            int col = n0 + wn + nt * 8 + c2;
            if (col < N) {
                float b0 = (bias != nullptr) ? bias[col] : 0.0f;
                float b1 = (bias != nullptr) ? bias[col + 1] : 0.0f;
                int row0 = m0 + wm + mt * 16 + r;
                float2 v0 = make_float2(acc[mt][nt][0] + b0, acc[mt][nt][1] + b1);
                float2 v1 = make_float2(acc[mt][nt][2] + b0, acc[mt][nt][3] + b1);
                *(float2*)&Cm[(size_t)row0 * ldc + col] = v0;
                *(float2*)&Cm[(size_t)(row0 + 8) * ldc + col] = v1;
            }
        }
    }
}

// ------------- TF32 out-GEMM: M=128, BN=80 (10000 = 125 x 80, single wave) ---
// 8 warps as 4M x 2N, warp tile 32x40. K % 32 == 0.
__global__ __launch_bounds__(256) void tgemm80(
    const float* __restrict__ A, int lda,
    const float* __restrict__ Bm, int ldb,
    const float* __restrict__ bias,
    float* __restrict__ Cm, long long ldc, int K) {
    __shared__ float As[128][36];
    __shared__ float Bs[80][36];
    const int tid = threadIdx.x, lane = tid & 31, wid = tid >> 5;
    const int n0 = blockIdx.x * 80;
    const int wm = (wid & 3) * 32, wn = (wid >> 2) * 40;

    const int am = tid >> 1, akh = (tid & 1) * 16;      // A: 16 floats/thread
    const bool bth = tid < 160;
    const int bn = tid >> 1, bkh = (tid & 1) * 16;      // B: 16 floats/thread (tid<160)

    float4 pa[4], pb[4];
    {
        const float* Ap = A + (size_t)am * lda + akh;
#pragma unroll
        for (int q = 0; q < 4; q++) pa[q] = *(const float4*)(Ap + q * 4);
        if (bth) {
            const float* Bp = Bm + (size_t)(n0 + bn) * ldb + bkh;
#pragma unroll
            for (int q = 0; q < 4; q++) pb[q] = *(const float4*)(Bp + q * 4);
        }
    }

    float acc[2][5][4];
#pragma unroll
    for (int mt = 0; mt < 2; mt++)
#pragma unroll
        for (int nt = 0; nt < 5; nt++)
#pragma unroll
            for (int q = 0; q < 4; q++) acc[mt][nt][q] = 0.0f;

    const int KT = K / 32;
    for (int kt = 0; kt < KT; kt++) {
#pragma unroll
        for (int q = 0; q < 4; q++) {
            As[am][akh + q * 4 + 0] = to_tf32(pa[q].x);
            As[am][akh + q * 4 + 1] = to_tf32(pa[q].y);
            As[am][akh + q * 4 + 2] = to_tf32(pa[q].z);
            As[am][akh + q * 4 + 3] = to_tf32(pa[q].w);
        }
        if (bth) {
#pragma unroll
            for (int q = 0; q < 4; q++) {
                Bs[bn][bkh + q * 4 + 0] = to_tf32(pb[q].x);
                Bs[bn][bkh + q * 4 + 1] = to_tf32(pb[q].y);
                Bs[bn][bkh + q * 4 + 2] = to_tf32(pb[q].z);
                Bs[bn][bkh + q * 4 + 3] = to_tf32(pb[q].w);
            }
        }
        __syncthreads();

        if (kt + 1 < KT) {
            int k0 = (kt + 1) * 32;
            const float* Ap = A + (size_t)am * lda + k0 + akh;
#pragma unroll
            for (int q = 0; q < 4; q++) pa[q] = *(const float4*)(Ap + q * 4);
            if (bth) {
                const float* Bp = Bm + (size_t)(n0 + bn) * ldb + k0 + bkh;
#pragma unroll
                for (int q = 0; q < 4; q++) pb[q] = *(const float4*)(Bp + q * 4);
            }
        }

        const int r = lane >> 2, c = lane & 3;
#pragma unroll
        for (int kc = 0; kc < 32; kc += 8) {
            uint32_t af[2][4], bf[5][2];
#pragma unroll
            for (int mt = 0; mt < 2; mt++) {
                int rb = wm + mt * 16;
                af[mt][0] = __float_as_uint(As[rb + r][kc + c]);
                af[mt][1] = __float_as_uint(As[rb + r + 8][kc + c]);
                af[mt][2] = __float_as_uint(As[rb + r][kc + c + 4]);
                af[mt][3] = __float_as_uint(As[rb + r + 8][kc + c + 4]);
            }
#pragma unroll
            for (int nt = 0; nt < 5; nt++) {
                int cb = wn + nt * 8;
                bf[nt][0] = __float_as_uint(Bs[cb + r][kc + c]);
                bf[nt][1] = __float_as_uint(Bs[cb + r][kc + c + 4]);
            }
#pragma unroll
            for (int mt = 0; mt < 2; mt++)
#pragma unroll
                for (int nt = 0; nt < 5; nt++)
                    mma_tf32(acc[mt][nt], af[mt], bf[nt]);
        }
        __syncthreads();
    }

    const int r = lane >> 2, c2 = (lane & 3) * 2;
#pragma unroll
    for (int mt = 0; mt < 2; mt++) {
#pragma unroll
        for (int nt = 0; nt < 5; nt++) {
            int col = n0 + wn + nt * 8 + c2;
            float b0 = bias[col], b1 = bias[col + 1];
            int row0 = wm + mt * 16 + r;
            float2 v0 = make_float2(acc[mt][nt][0] + b0, acc[mt][nt][1] + b1);
            float2 v1 = make_float2(acc[mt][nt][2] + b0, acc[mt][nt][3] + b1);
            *(float2*)&Cm[(size_t)row0 * ldc + col] = v0;
            *(float2*)&Cm[(size_t)(row0 + 8) * ldc + col] = v1;
        }
    }
}

// ------------- SGEMM BN=16 body (fp32, recurrence-critical small GEMMs) ------
__device__ __forceinline__ void sgemm16_body(
    const float* __restrict__ A, int lda,
    const float* __restrict__ Bm, int ldb,
    const float* __restrict__ bias,
    float* __restrict__ Cm, int ldc, int K, int nblk,
    float (*As)[132], float (*Bs)[17]) {
    int tid = threadIdx.x;
    int tx = tid & 15, ty = tid >> 4;
    int n0 = nblk * 16;

    float acc[8];
#pragma unroll
    for (int i = 0; i < 8; i++) acc[i] = 0.0f;

    for (int k0 = 0; k0 < K; k0 += 16) {
#pragma unroll
        for (int i = 0; i < 2; i++) {
            int idx = tid + i * 256;
            int m = idx >> 2, kq = idx & 3;
            float4 a = *(const float4*)&A[(size_t)m * lda + k0 + kq * 4];
            As[kq * 4 + 0][m] = a.x; As[kq * 4 + 1][m] = a.y;
            As[kq * 4 + 2][m] = a.z; As[kq * 4 + 3][m] = a.w;
        }
        if (tid < 64) {
            int n = tid >> 2, kq = tid & 3;
            float4 bv = *(const float4*)&Bm[(size_t)(n0 + n) * ldb + k0 + kq * 4];
            Bs[kq * 4 + 0][n] = bv.x; Bs[kq * 4 + 1][n] = bv.y;
            Bs[kq * 4 + 2][n] = bv.z; Bs[kq * 4 + 3][n] = bv.w;
        }
        __syncthreads();
#pragma unroll
        for (int kk = 0; kk < 16; kk++) {
            float4 a0 = *(const float4*)&As[kk][ty * 4];
            float4 a1 = *(const float4*)&As[kk][64 + ty * 4];
            float b = Bs[kk][tx];
            acc[0] += a0.x * b; acc[1] += a0.y * b;
            acc[2] += a0.z * b; acc[3] += a0.w * b;
            acc[4] += a1.x * b; acc[5] += a1.y * b;
            acc[6] += a1.z * b; acc[7] += a1.w * b;
        }
        __syncthreads();
    }
    int n = n0 + tx;
    float bv = (bias != nullptr) ? bias[n] : 0.0f;
#pragma unroll
    for (int r = 0; r < 8; r++) {
        int m = (r < 4) ? (ty * 4 + r) : (64 + ty * 4 + (r - 4));
        Cm[(size_t)m * ldc + n] = acc[r] + bv;
    }
}

__global__ __launch_bounds__(256) void sgemm16(
    const float* __restrict__ A, int lda,
    const float* __restrict__ Bm, int ldb,
    const float* __restrict__ bias,
    float* __restrict__ Cm, int ldc, int K) {
    __shared__ float As[16][132];
    __shared__ float Bs[16][17];
    sgemm16_body(A, lda, Bm, ldb, bias, Cm, ldc, K, blockIdx.x, As, Bs);
}

// fused gi + gh GEMMs: blocks [0,96) -> gi, [96,192) -> gh
__global__ __launch_bounds__(256) void gigh_kernel(
    const float* __restrict__ Wih, const float* __restrict__ bih,
    const float* __restrict__ Whh, const float* __restrict__ bhh) {
    __shared__ float As[16][132];
    __shared__ float Bs[16][17];
    if (blockIdx.x < 96)
        sgemm16_body(&g.x[0][0], 768, Wih, 768, bih, &g.gi[0][0], 1536, 768,
                     blockIdx.x, As, Bs);
    else
        sgemm16_body(&g.hdec[0][0], 512, Whh, 512, bhh, &g.gh[0][0], 1536, 512,
                     blockIdx.x - 96, As, Bs);
}

// ---------------- encoder recurrence: persistent kernel ----------------------
__global__ __launch_bounds__(256, 1) void enc_scan_kernel(
    const float* __restrict__ Whh_f, const float* __restrict__ bhh_f,
    const float* __restrict__ Whh_b, const float* __restrict__ bhh_b) {
    int dir = blockIdx.x >> 6;
    int e0 = (blockIdx.x & 63) * 4;
    const float* Whh = dir ? Whh_b : Whh_f;
    const float* bhh = dir ? bhh_b : bhh_f;

    __shared__ float ws[4][256];
    __shared__ float hs[128][68];
    int tid = threadIdx.x;

    {
        float* gh = &g.h[0][0][0][0];
        int base = blockIdx.x * 256 + tid;
#pragma unroll
        for (int i = 0; i < 4; i++) gh[base + i * 32768] = 0.0f;
    }
    {
        int r = tid >> 6, kv = tid & 63;
        *(float4*)&ws[r][kv * 4] = *(const float4*)&Whh[(e0 + r) * 256 + kv * 4];
    }
    int b = tid & 127;
    int j0 = (tid >> 7) * 2;
    float bh0 = bhh[e0 + j0], bh1 = bhh[e0 + j0 + 1];

    grid_barrier(128);

    for (int t = 0; t < 128; t++) {
        int s = dir ? (127 - t) : t;
        int p = t & 1;
        const float* hin = &g.h[dir][p][0][0];
        float acc0 = 0.f, acc1 = 0.f;
#pragma unroll 1
        for (int c = 0; c < 4; c++) {
#pragma unroll
            for (int i = 0; i < 8; i++) {
                int idx = tid + i * 256;
                int bb = idx >> 4, kv = idx & 15;
                float4 hv = __ldcg((const float4*)&hin[bb * 256 + c * 64 + kv * 4]);
                *(float4*)&hs[bb][kv * 4] = hv;
            }
            __syncthreads();
#pragma unroll
            for (int kv = 0; kv < 16; kv++) {
                float4 hv = *(const float4*)&hs[b][kv * 4];
                float4 w0 = *(const float4*)&ws[j0][c * 64 + kv * 4];
                float4 w1 = *(const float4*)&ws[j0 + 1][c * 64 + kv * 4];
                acc0 += hv.x * w0.x + hv.y * w0.y + hv.z * w0.z + hv.w * w0.w;
                acc1 += hv.x * w1.x + hv.y * w1.y + hv.z * w1.z + hv.w * w1.w;
            }
            __syncthreads();
        }
        float h0 = tanh_fast(g.pre[dir][s * 128 + b][e0 + j0] + acc0 + bh0);
        float h1 = tanh_fast(g.pre[dir][s * 128 + b][e0 + j0 + 1] + acc1 + bh1);
        float* hout = &g.h[dir][1 - p][0][0];
        hout[b * 256 + e0 + j0] = h0;
        hout[b * 256 + e0 + j0 + 1] = h1;
        g.enc_out[s * 128 + b][dir * 256 + e0 + j0] = h0;
        g.enc_out[s * 128 + b][dir * 256 + e0 + j0 + 1] = h1;
        grid_barrier(128);
    }
}

__global__ void concat_h_kernel() {
    int idx = blockIdx.x * 256 + threadIdx.x;   // 65536
    int b = idx >> 9, e = idx & 511;
    g.hcat[b][e] = (e < 256) ? g.h[0][0][b][e] : g.h[1][0][b][e - 256];
}

__global__ void act_hdec_kernel() {             // hdec = tanh(fc_tmp in g.gi)
    int idx = blockIdx.x * 256 + threadIdx.x;   // 65536
    int b = idx >> 9, d = idx & 511;
    g.hdec[b][d] = tanh_fast((&g.gi[0][0])[idx]);
}

// ---------------- decoder step kernels ---------------------------------------
__global__ void embed_kernel(const int* __restrict__ trg,
                             const float* __restrict__ emb, int t) {
    int b = blockIdx.x, e = threadIdx.x;        // 128 x 256
    int tok = trg[b * T_ + t];
    float val = emb[(size_t)tok * EMB_ + e];
    g.x[b][e] = val;
    g.z[b][1024 + e] = val;
}

// fused attention: scores (tanh energy . v), softmax over S, weighted context.
// 1 CTA per batch row b, 256 threads.
__global__ __launch_bounds__(256) void attn_fused_kernel(const float* __restrict__ v) {
    int b = blockIdx.x;
    int tid = threadIdx.x;
    __shared__ float hw_s[512], vs[512];
    __shared__ float sc[128], aw[128], red[128];
    hw_s[tid] = g.hW[b][tid];
    hw_s[tid + 256] = g.hW[b][tid + 256];
    vs[tid] = v[tid];
    vs[tid + 256] = v[tid + 256];
    __syncthreads();
    int w = tid >> 5, lane = tid & 31;
#pragma unroll 1
    for (int si = w; si < 128; si += 8) {
        const float* ep = &g.enc_part[si * 128 + b][0];
        float val = 0.f;
#pragma unroll
        for (int dd = 0; dd < 16; dd++) {
            int d = lane + dd * 32;
            val += tanh_fast(hw_s[d] + ep[d]) * vs[d];
        }
#pragma unroll
        for (int o = 16; o > 0; o >>= 1) val += __shfl_xor_sync(0xffffffffu, val, o);
        if (lane == 0) sc[si] = val;
    }
    __syncthreads();
    float xv = 0.f;
    if (tid < 128) { xv = sc[tid]; red[tid] = xv; }
    __syncthreads();
    for (int o = 64; o > 0; o >>= 1) {
        if (tid < o) red[tid] = fmaxf(red[tid], red[tid + o]);
        __syncthreads();
    }
    float mx = red[0];
    __syncthreads();
    float e = 0.f;
    if (tid < 128) { e = __expf(xv - mx); red[tid] = e; }
    __syncthreads();
    for (int o = 64; o > 0; o >>= 1) {
        if (tid < o) red[tid] += red[tid + o];
        __syncthreads();
    }
    float inv = 1.0f / red[0];
    if (tid < 128) aw[tid] = e * inv;
    __syncthreads();
    float a0 = 0.f, a1 = 0.f;
#pragma unroll 8
    for (int s2 = 0; s2 < 128; s2++) {
        float as = aw[s2];
        const float* eo = &g.enc_out[s2 * 128 + b][0];
        a0 += as * eo[tid];
        a1 += as * eo[tid + 256];
    }
    g.x[b][256 + tid] = a0;
    g.x[b][256 + tid + 256] = a1;
    g.z[b][512 + tid] = a0;
    g.z[b][512 + tid + 256] = a1;
}

__global__ void gru_combine_kernel() {
    int idx = blockIdx.x * 256 + threadIdx.x;   // 65536
    int b = idx >> 9, d = idx & 511;
    float r = sig_fast(g.gi[b][d] + g.gh[b][d]);
    float zz = sig_fast(g.gi[b][512 + d] + g.gh[b][512 + d]);
    float n = tanh_fast(g.gi[b][1024 + d] + r * g.gh[b][1024 + d]);
    float h = g.hdec[b][d];
    float hn = (1.0f - zz) * n + zz * h;
    g.hdec[b][d] = hn;
    g.z[b][d] = hn;
}

// single-pass register-resident softmax over V=10000
__global__ __launch_bounds__(256) void out_softmax_kernel(float* __restrict__ outp, int t) {
    int b = blockIdx.x;
    int tid = threadIdx.x;
    float* row = outp + ((size_t)(b * T_ + t)) * V_;
    __shared__ float sh[256];
    float r[40];
    float mx = -1e30f;
#pragma unroll
    for (int j = 0; j < 40; j++) {
        int i = tid + j * 256;
        r[j] = (i < V_) ? row[i] : -1e30f;
        mx = fmaxf(mx, r[j]);
    }
    sh[tid] = mx;
    __syncthreads();
    for (int o = 128; o > 0; o >>= 1) {
        if (tid < o) sh[tid] = fmaxf(sh[tid], sh[tid + o]);
        __syncthreads();
    }
    mx = sh[0];
    __syncthreads();
    float sum = 0.f;
#pragma unroll
    for (int j = 0; j < 40; j++) {
        r[j] = __expf(r[j] - mx);
        sum += r[j];
    }
    sh[tid] = sum;
    __syncthreads();
    for (int o = 128; o > 0; o >>= 1) {
        if (tid < o) sh[tid] += sh[tid + o];
        __syncthreads();
    }
    float inv = 1.0f / sh[0];
#pragma unroll
    for (int j = 0; j < 40; j++) {
        int i = tid + j * 256;
        if (i < V_) row[i] = r[j] * inv;
    }
}

// -----------------------------------------------------------------------------
extern "C" void kernel_launch(void* const* d_in, const int* in_sizes, int n_in,
                              void* d_out, int out_size) {
    Scratch* gp;
    cudaGetSymbolAddress((void**)&gp, g);

    const float* src      = (const float*)d_in[0];
    const int*   trg      = (const int*)  d_in[1];
    const float* Wih_f    = (const float*)d_in[2];
    const float* Whh_f    = (const float*)d_in[3];
    const float* bih_f    = (const float*)d_in[4];
    const float* bhh_f    = (const float*)d_in[5];
    const float* Wih_b    = (const float*)d_in[6];
    const float* Whh_b    = (const float*)d_in[7];
    const float* bih_b    = (const float*)d_in[8];
    const float* bhh_b    = (const float*)d_in[9];
    const float* fcW      = (const float*)d_in[10];
    const float* fcb      = (const float*)d_in[11];
    const float* attn_W   = (const float*)d_in[12];
    const float* attn_b   = (const float*)d_in[13];
    const float* attn_v   = (const float*)d_in[14];
    const float* emb      = (const float*)d_in[15];
    const float* gru_Wih  = (const float*)d_in[16];
    const float* gru_Whh  = (const float*)d_in[17];
    const float* gru_bih  = (const float*)d_in[18];
    const float* gru_bhh  = (const float*)d_in[19];
    const float* out_W    = (const float*)d_in[20];
    const float* out_b    = (const float*)d_in[21];
    float* out = (float*)d_out;

    float* pre_f    = &gp->pre[0][0][0];
    float* pre_b    = &gp->pre[1][0][0];
    float* enc_out  = &gp->enc_out[0][0];
    float* enc_part = &gp->enc_part[0][0];
    float* hcat     = &gp->hcat[0][0];
    float* hdec     = &gp->hdec[0][0];
    float* hW       = &gp->hW[0][0];
    float* zbuf     = &gp->z[0][0];
    float* gi       = &gp->gi[0][0];

    // ---- encoder ----
    tgemm_tf32<<<dim3(4, 128), 256>>>(src, C_, Wih_f, C_, bih_f, pre_f, E_, E_, C_);
    tgemm_tf32<<<dim3(4, 128), 256>>>(src, C_, Wih_b, C_, bih_b, pre_b, E_, E_, C_);
    enc_scan_kernel<<<128, 256>>>(Whh_f, bhh_f, Whh_b, bhh_b);
    concat_h_kernel<<<256, 256>>>();
    sgemm16<<<32, 256>>>(hcat, 512, fcW, 512, fcb, gi, 512, 512);   // fc tmp in gi
    act_hdec_kernel<<<256, 256>>>();
    tgemm_tf32<<<dim3(8, 128), 256>>>(enc_out, 512, attn_W + 512, 1024, attn_b,
                                      enc_part, D_, D_, 512);

    // ---- decoder ----
    for (int t = 0; t < T_; t++) {
        embed_kernel<<<128, 256>>>(trg, emb, t);
        sgemm16<<<32, 256>>>(hdec, 512, attn_W, 1024, nullptr, hW, 512, 512);
        attn_fused_kernel<<<128, 256>>>(attn_v);
        gigh_kernel<<<192, 256>>>(gru_Wih, gru_bih, gru_Whh, gru_bhh);
        gru_combine_kernel<<<256, 256>>>();
        tgemm80<<<125, 256>>>(zbuf, 1280, out_W, 1280, out_b,
                              out + (size_t)t * V_, (long long)T_ * V_, 1280);
        out_softmax_kernel<<<128, 256>>>(out, t);
    }
}